// round 8
// baseline (speedup 1.0000x reference)
#include <cuda_runtime.h>
#include <cstdint>

// ============================================================
// SVDDecomposeTransMatrix — fused persistent kernel, round 7.
//   Blocks 0-3: Cayley (Horner, k<8) + compose -> g_ML/g_MR, flags.
//   Blocks 4+ : L2-prefetch x while waiting.
//   Then ALL 608 blocks (128 thr, 4/SM): batched 64x64 TF32 GEMM,
//   static stride, loop-interchanged mma (no serial HMMA chains).
// ============================================================

#define MSTR 68   // prep smem stride
#define SSTR 72   // kron smem stride (conflict-free fragment reads)
#define NBLK 608  // 152 SMs * 4 -> all resident in wave 1 (spin-safe)

__device__ float g_scr[4][2][4096]; // per-prep-block scratch (P, R)
__device__ float g_Qv[2][4096];     // Cayley(v_left), Cayley(v_right)
__device__ float g_ML[4096];        // TRANSPOSED m_left
__device__ float g_MR[4096];        // m_right row-major
__device__ int g_qdone[2];
__device__ int g_mdone;

__global__ void reset_kernel() { g_qdone[0] = 0; g_qdone[1] = 0; g_mdone = 0; }

__device__ __forceinline__ int ld_acquire(const int* p) {
    int v; asm volatile("ld.acquire.gpu.b32 %0, [%1];" : "=r"(v) : "l"(p)); return v;
}
__device__ __forceinline__ int ld_relaxed(const int* p) {
    int v; asm volatile("ld.relaxed.gpu.b32 %0, [%1];" : "=r"(v) : "l"(p)); return v;
}

// C = A*B (+B if ADD), 64x64. Strides per matrix. 128 threads, 4x8 tiles.
template <int SA, int SB, int SC, bool ADD>
__device__ __forceinline__ void mm128(const float* __restrict__ A,
                                      const float* __restrict__ B,
                                      float* __restrict__ C, int tid) {
    int r0 = (tid >> 3) * 4;
    int c0 = (tid & 7) * 8;
    float acc[4][8];
#pragma unroll
    for (int i = 0; i < 4; ++i)
#pragma unroll
        for (int j = 0; j < 8; ++j) acc[i][j] = 0.f;
#pragma unroll 4
    for (int k = 0; k < 64; ++k) {
        float4 bl = *(const float4*)&B[k * SB + c0];
        float4 bh = *(const float4*)&B[k * SB + c0 + 4];
        float bv[8] = {bl.x, bl.y, bl.z, bl.w, bh.x, bh.y, bh.z, bh.w};
#pragma unroll
        for (int i = 0; i < 4; ++i) {
            float a = A[(r0 + i) * SA + k];
#pragma unroll
            for (int j = 0; j < 8; ++j) acc[i][j] += a * bv[j];
        }
    }
#pragma unroll
    for (int i = 0; i < 4; ++i) {
        if (ADD) {
#pragma unroll
            for (int j = 0; j < 8; ++j) acc[i][j] += B[(r0 + i) * SB + c0 + j];
        }
        *(float4*)&C[(r0 + i) * SC + c0]     = make_float4(acc[i][0], acc[i][1], acc[i][2], acc[i][3]);
        *(float4*)&C[(r0 + i) * SC + c0 + 4] = make_float4(acc[i][4], acc[i][5], acc[i][6], acc[i][7]);
    }
}

__device__ __forceinline__ unsigned f2tf(float f) {
    unsigned u; asm("cvt.rna.tf32.f32 %0, %1;" : "=r"(u) : "f"(f)); return u;
}

__device__ __forceinline__ void mma_tf32(float& d0, float& d1, float& d2, float& d3,
                                         unsigned a0, unsigned a1, unsigned a2, unsigned a3,
                                         unsigned b0, unsigned b1) {
    asm volatile(
        "mma.sync.aligned.m16n8k8.row.col.f32.tf32.tf32.f32 "
        "{%0,%1,%2,%3}, {%4,%5,%6,%7}, {%8,%9}, {%0,%1,%2,%3};\n"
        : "+f"(d0), "+f"(d1), "+f"(d2), "+f"(d3)
        : "r"(a0), "r"(a1), "r"(a2), "r"(a3), "r"(b0), "r"(b1));
}

__global__ __launch_bounds__(128, 4)
void fused_kernel(const float* __restrict__ x,
                  const float* __restrict__ u_left,
                  const float* __restrict__ v_left,
                  const float* __restrict__ diag_left,
                  const float* __restrict__ u_right,
                  const float* __restrict__ v_right,
                  const float* __restrict__ diag_right,
                  const float* __restrict__ diag_scale,
                  float* __restrict__ out, int ntiles) {
    extern __shared__ float sm[];
    int tid = threadIdx.x;
    int bid = blockIdx.x;

    // ================= PHASE 1: prep (blocks 0-3) / L2 prefetch (others) ======
    if (bid < 4) {
        // Cayley, series k<8: Q = (I+B)(I+B)(I+B^2)(I+B^4), B = A/2.
        // ||B|| ~ 0.16 -> truncation ~4e-7 << tf32 noise.
        float* sB = sm;                 // smem, stride MSTR
        float* sR = sm + 64 * MSTR;     // smem, stride MSTR
        float* gP = g_scr[bid][0];      // global, stride 64
        float* gR = g_scr[bid][1];      // global, stride 64
        const float* X = (bid == 0) ? u_left : (bid == 1) ? v_left :
                         (bid == 2) ? u_right : v_right;
        for (int idx = tid; idx < 4096; idx += 128) {
            int i = idx >> 6, j = idx & 63;
            float a = (i > j) ? X[i * 64 + j] : (i < j ? -X[j * 64 + i] : 0.f);
            float b = 0.5f * a;
            sB[i * MSTR + j] = b;
            sR[i * MSTR + j] = (i == j) ? 1.f + b : b;   // R0 = I + B
        }
        __syncthreads();
        mm128<MSTR, MSTR, 64, true >(sB, sR, gR, tid);   // gR = (I+B)R0
        mm128<MSTR, MSTR, 64, false>(sB, sB, gP, tid);   // gP = B^2
        __syncthreads();
        mm128<64, 64, MSTR, true >(gP, gR, sR, tid);     // sR = (I+B^2)R
        mm128<64, 64, MSTR, false>(gP, gP, sB, tid);     // sB = B^4
        __syncthreads();

        if (bid == 1 || bid == 3) {
            // final: Q -> g_Qv directly
            mm128<MSTR, MSTR, 64, true>(sB, sR, g_Qv[bid >> 1], tid);
            __threadfence();
            __syncthreads();
            if (tid == 0) atomicExch(&g_qdone[bid >> 1], 1);
        } else {
            mm128<MSTR, MSTR, 64, true>(sB, sR, gR, tid);  // gR = Q_u
            if (tid == 0) { while (ld_acquire(&g_qdone[bid >> 1]) == 0) __nanosleep(64); }
            __syncthreads();
            const float* Qv = g_Qv[bid >> 1];
            const float* d  = (bid == 0) ? diag_left : diag_right;
            for (int idx = tid; idx < 4096; idx += 128) {
                int i = idx >> 6, j = idx & 63;
                sB[i * MSTR + j] = d[i] * Qv[idx];       // D = diag*Qv
            }
            __syncthreads();
            mm128<64, MSTR, 64, false>(gR, sB, gP, tid); // M = Q_u @ D
            __syncthreads();
            for (int idx = tid; idx < 4096; idx += 128) {
                int a = idx >> 6, b = idx & 63;
                float v = gP[a * 64 + b];
                if (bid == 0) g_ML[b * 64 + a] = v;      // m_left transposed
                else          g_MR[a * 64 + b] = v;
            }
            __threadfence();
            __syncthreads();
            if (tid == 0) atomicAdd(&g_mdone, 1);
        }
    } else {
        // warm L2 with x while prep runs (128 thr * 128B = one 16KB tile/iter)
        const char* xb = (const char*)x;
        for (int q = bid; q < ntiles; q += NBLK) {
            if (ld_relaxed(&g_mdone) >= 2) break;
            const char* p = xb + (size_t)q * 16384 + tid * 128;
            asm volatile("prefetch.global.L2 [%0];" :: "l"(p));
        }
    }

    // ================= barrier on prep completion =================
    if (tid == 0) { while (ld_acquire(&g_mdone) < 2) __nanosleep(32); }
    __syncthreads();

    // ================= PHASE 2: kron GEMMs (round-4 structure + interchange) ==
    float* sDiag = sm;                       // 4096 fp32
    float* sMR   = sm + 4096;                // 64*SSTR tf32 bits
    float* sXs   = sMR + 64 * SSTR;          // 64*SSTR tf32 bits; T in-place

    int warp = tid >> 5, lane = tid & 31;
    int g = lane >> 2, t4 = lane & 3;
    int strip = warp * 16;                   // this warp's 16 output rows

    for (int i = tid; i < 4096; i += 128) {
        sDiag[i] = diag_scale[i];
        int r = i >> 6, c = i & 63;
        sMR[r * SSTR + c] = __uint_as_float(f2tf(g_MR[i]));
    }
    unsigned a1f[8][4];
#pragma unroll
    for (int kk = 0; kk < 8; ++kk) {
        int i0 = kk * 8 + t4;
        a1f[kk][0] = f2tf(g_ML[(strip + g)     * 64 + i0]);
        a1f[kk][1] = f2tf(g_ML[(strip + g + 8) * 64 + i0]);
        a1f[kk][2] = f2tf(g_ML[(strip + g)     * 64 + i0 + 4]);
        a1f[kk][3] = f2tf(g_ML[(strip + g + 8) * 64 + i0 + 4]);
    }
    __syncthreads();

    int t = bid;
    float4 pf[8];
    if (t < ntiles) {
        const float4* xt = (const float4*)(x + (size_t)t * 4096);
#pragma unroll
        for (int it = 0; it < 8; ++it) pf[it] = xt[it * 128 + tid];
    }

    const float4* dg = (const float4*)sDiag;
    while (t < ntiles) {
        // ---- stage Xs = x_tile * diag_scale (tf32 bits) ----
#pragma unroll
        for (int it = 0; it < 8; ++it) {
            int idx = it * 128 + tid;
            float4 v = pf[it];
            float4 s = dg[idx];
            uint4 pk = make_uint4(f2tf(v.x * s.x), f2tf(v.y * s.y),
                                  f2tf(v.z * s.z), f2tf(v.w * s.w));
            int row = idx >> 4, col = (idx & 15) << 2;
            *(uint4*)&sXs[row * SSTR + col] = pk;
        }
        __syncthreads();

        // ---- issue next tile's loads early ----
        int tn = t + NBLK;
        if (tn < ntiles) {
            const float4* xtn = (const float4*)(x + (size_t)tn * 4096);
#pragma unroll
            for (int it = 0; it < 8; ++it) pf[it] = xtn[it * 128 + tid];
        }

        // ---- GEMM1: T_strip = (M_L^T)_strip @ Xs  (kk outer -> independent mmas)
        float c1[8][4];
#pragma unroll
        for (int nn = 0; nn < 8; ++nn) {
            c1[nn][0] = 0.f; c1[nn][1] = 0.f; c1[nn][2] = 0.f; c1[nn][3] = 0.f;
        }
#pragma unroll
        for (int kk = 0; kk < 8; ++kk) {
#pragma unroll
            for (int nn = 0; nn < 8; ++nn) {
                unsigned b0 = __float_as_uint(sXs[(kk * 8 + t4)     * SSTR + nn * 8 + g]);
                unsigned b1 = __float_as_uint(sXs[(kk * 8 + t4 + 4) * SSTR + nn * 8 + g]);
                mma_tf32(c1[nn][0], c1[nn][1], c1[nn][2], c1[nn][3],
                         a1f[kk][0], a1f[kk][1], a1f[kk][2], a1f[kk][3], b0, b1);
            }
        }
        __syncthreads();   // all reads of Xs done -> overwrite with T

        // ---- write T strip in-place ----
#pragma unroll
        for (int nn = 0; nn < 8; ++nn) {
            *(uint2*)&sXs[(strip + g)     * SSTR + nn * 8 + 2 * t4] =
                make_uint2(f2tf(c1[nn][0]), f2tf(c1[nn][1]));
            *(uint2*)&sXs[(strip + g + 8) * SSTR + nn * 8 + 2 * t4] =
                make_uint2(f2tf(c1[nn][2]), f2tf(c1[nn][3]));
        }
        __syncwarp();   // strip is warp-private

        unsigned a2f[8][4];
#pragma unroll
        for (int kk = 0; kk < 8; ++kk) {
            int j0 = kk * 8 + t4;
            a2f[kk][0] = __float_as_uint(sXs[(strip + g)     * SSTR + j0]);
            a2f[kk][1] = __float_as_uint(sXs[(strip + g + 8) * SSTR + j0]);
            a2f[kk][2] = __float_as_uint(sXs[(strip + g)     * SSTR + j0 + 4]);
            a2f[kk][3] = __float_as_uint(sXs[(strip + g + 8) * SSTR + j0 + 4]);
        }

        // ---- GEMM2: O_strip = T_strip @ M_R  (kk outer -> independent mmas)
        float c2[8][4];
#pragma unroll
        for (int nn = 0; nn < 8; ++nn) {
            c2[nn][0] = 0.f; c2[nn][1] = 0.f; c2[nn][2] = 0.f; c2[nn][3] = 0.f;
        }
#pragma unroll
        for (int kk = 0; kk < 8; ++kk) {
#pragma unroll
            for (int nn = 0; nn < 8; ++nn) {
                unsigned b0 = __float_as_uint(sMR[(kk * 8 + t4)     * SSTR + nn * 8 + g]);
                unsigned b1 = __float_as_uint(sMR[(kk * 8 + t4 + 4) * SSTR + nn * 8 + g]);
                mma_tf32(c2[nn][0], c2[nn][1], c2[nn][2], c2[nn][3],
                         a2f[kk][0], a2f[kk][1], a2f[kk][2], a2f[kk][3], b0, b1);
            }
        }

        // ---- coalesced store ----
        float* ot = out + (size_t)t * 4096;
#pragma unroll
        for (int nn = 0; nn < 8; ++nn) {
            int row = strip + g, col = nn * 8 + 2 * t4;
            *(float2*)&ot[row * 64 + col]       = make_float2(c2[nn][0], c2[nn][1]);
            *(float2*)&ot[(row + 8) * 64 + col] = make_float2(c2[nn][2], c2[nn][3]);
        }
        __syncthreads();   // T consumed -> next staging may overwrite
        t = tn;
    }
}

// ---------------- launch ----------------
extern "C" void kernel_launch(void* const* d_in, const int* in_sizes, int n_in,
                              void* d_out, int out_size) {
    const float* x          = (const float*)d_in[0];
    const float* u_left     = (const float*)d_in[1];
    const float* v_left     = (const float*)d_in[2];
    const float* diag_left  = (const float*)d_in[3];
    const float* u_right    = (const float*)d_in[4];
    const float* v_right    = (const float*)d_in[5];
    const float* diag_right = (const float*)d_in[6];
    const float* diag_scale = (const float*)d_in[7];
    float* out = (float*)d_out;

    int ntiles = in_sizes[0] / 4096;

    // smem: max(prep 2*64*68, kron 4096+2*64*72) = 13312 floats = 53248 B
    const int SMEM_BYTES = (4096 + 2 * 64 * SSTR) * (int)sizeof(float);
    cudaFuncSetAttribute(fused_kernel, cudaFuncAttributeMaxDynamicSharedMemorySize, SMEM_BYTES);

    reset_kernel<<<1, 1>>>();
    fused_kernel<<<NBLK, 128, SMEM_BYTES>>>(x, u_left, v_left, diag_left,
                                            u_right, v_right, diag_right,
                                            diag_scale, out, ntiles);
}

// round 11
// speedup vs baseline: 1.0529x; 1.0529x over previous
#include <cuda_runtime.h>
#include <cstdint>

// ============================================================
// SVDDecomposeTransMatrix — round 10.
//   prep_kernel: 4 blocks, all-smem Horner Cayley (k<8) + flag-synced
//                compose -> g_ML (transposed), g_MR.
//   kron_kernel: round-4 proven structure (127.5us) + kk-outer mma
//                interchange (independent HMMA accumulator chains).
// ============================================================

#define PSTR 68   // prep smem stride
#define SSTR 72   // kron smem stride (conflict-free fragment reads)
#define NBLK 608  // 152 SMs * 4

__device__ float g_Qv[2][4096];   // Cayley(v_left), Cayley(v_right)
__device__ float g_ML[4096];      // TRANSPOSED m_left: g_ML[l*64+i] = m_left[i][l]
__device__ float g_MR[4096];      // m_right row-major
__device__ int   g_qdone[2];

__global__ void reset_kernel() { g_qdone[0] = 0; g_qdone[1] = 0; }

__device__ __forceinline__ int ld_acquire(const int* p) {
    int v; asm volatile("ld.acquire.gpu.b32 %0, [%1];" : "=r"(v) : "l"(p)); return v;
}

// C = A*B (+B if ADD), 64x64 all stride PSTR, 256 threads, 2x8 tiles.
template <bool ADD>
__device__ __forceinline__ void mm256(const float* __restrict__ A,
                                      const float* __restrict__ B,
                                      float* __restrict__ C, int tid) {
    int r0 = (tid >> 3) * 2;
    int c0 = (tid & 7) * 8;
    float a0[8] = {0,0,0,0,0,0,0,0};
    float a1[8] = {0,0,0,0,0,0,0,0};
#pragma unroll 8
    for (int k = 0; k < 64; ++k) {
        float4 bl = *(const float4*)&B[k * PSTR + c0];
        float4 bh = *(const float4*)&B[k * PSTR + c0 + 4];
        float x0 = A[r0 * PSTR + k];
        float x1 = A[(r0 + 1) * PSTR + k];
        a0[0]+=x0*bl.x; a0[1]+=x0*bl.y; a0[2]+=x0*bl.z; a0[3]+=x0*bl.w;
        a0[4]+=x0*bh.x; a0[5]+=x0*bh.y; a0[6]+=x0*bh.z; a0[7]+=x0*bh.w;
        a1[0]+=x1*bl.x; a1[1]+=x1*bl.y; a1[2]+=x1*bl.z; a1[3]+=x1*bl.w;
        a1[4]+=x1*bh.x; a1[5]+=x1*bh.y; a1[6]+=x1*bh.z; a1[7]+=x1*bh.w;
    }
    if (ADD) {
#pragma unroll
        for (int j = 0; j < 8; ++j) {
            a0[j] += B[r0 * PSTR + c0 + j];
            a1[j] += B[(r0 + 1) * PSTR + c0 + j];
        }
    }
    *(float4*)&C[r0 * PSTR + c0]           = make_float4(a0[0],a0[1],a0[2],a0[3]);
    *(float4*)&C[r0 * PSTR + c0 + 4]       = make_float4(a0[4],a0[5],a0[6],a0[7]);
    *(float4*)&C[(r0 + 1) * PSTR + c0]     = make_float4(a1[0],a1[1],a1[2],a1[3]);
    *(float4*)&C[(r0 + 1) * PSTR + c0 + 4] = make_float4(a1[4],a1[5],a1[6],a1[7]);
}

// ---------------- prep: 4 blocks, all-smem Cayley + compose ----------------
// Q = (I+B)(I+B)(I+B^2)(I+B^4), B = A/2 (series k<8, trunc ~4e-7)
__global__ __launch_bounds__(256)
void prep_kernel(const float* __restrict__ u_left,
                 const float* __restrict__ v_left,
                 const float* __restrict__ diag_left,
                 const float* __restrict__ u_right,
                 const float* __restrict__ v_right,
                 const float* __restrict__ diag_right) {
    extern __shared__ float sm[];
    float* B = sm;
    float* P = B + 64 * PSTR;
    float* R = P + 64 * PSTR;
    float* T = R + 64 * PSTR;
    int tid = threadIdx.x, bid = blockIdx.x;
    const float* X = (bid == 0) ? u_left : (bid == 1) ? v_left :
                     (bid == 2) ? u_right : v_right;

    for (int idx = tid; idx < 4096; idx += 256) {
        int i = idx >> 6, j = idx & 63;
        float a = (i > j) ? X[i * 64 + j] : (i < j ? -X[j * 64 + i] : 0.f);
        float b = 0.5f * a;
        B[i * PSTR + j] = b;
        R[i * PSTR + j] = (i == j) ? 1.f + b : b;   // I + B
    }
    __syncthreads();
    mm256<true >(B, R, T, tid);    // T = (I+B)R
    mm256<false>(B, B, P, tid);    // P = B^2
    __syncthreads();
    mm256<true >(P, T, R, tid);    // R = (I+B^2)T
    mm256<false>(P, P, B, tid);    // B <- B^4
    __syncthreads();
    mm256<true >(B, R, T, tid);    // T = Q
    __syncthreads();

    if (bid == 1 || bid == 3) {
        float* dst = g_Qv[bid >> 1];
        for (int idx = tid; idx < 4096; idx += 256) {
            int i = idx >> 6, j = idx & 63;
            dst[idx] = T[i * PSTR + j];
        }
        __threadfence();
        __syncthreads();
        if (tid == 0) atomicExch(&g_qdone[bid >> 1], 1);
    } else {
        if (tid == 0) { while (ld_acquire(&g_qdone[bid >> 1]) == 0) __nanosleep(64); }
        __syncthreads();
        const float* Qv = g_Qv[bid >> 1];
        const float* d  = (bid == 0) ? diag_left : diag_right;
        for (int idx = tid; idx < 4096; idx += 256) {
            int i = idx >> 6, j = idx & 63;
            P[i * PSTR + j] = d[i] * Qv[idx];        // D = diag * Q_v
        }
        __syncthreads();
        mm256<false>(T, P, R, tid);                  // M = Q_u @ D
        __syncthreads();
        for (int idx = tid; idx < 4096; idx += 256) {
            int a = idx >> 6, b = idx & 63;
            float v = R[a * PSTR + b];
            if (bid == 0) g_ML[b * 64 + a] = v;      // m_left transposed
            else          g_MR[a * 64 + b] = v;
        }
    }
}

// ---------------- main: persistent batched 64x64x64x2 GEMM, TF32 mma -------
__device__ __forceinline__ unsigned f2tf(float f) {
    unsigned u; asm("cvt.rna.tf32.f32 %0, %1;" : "=r"(u) : "f"(f)); return u;
}

__device__ __forceinline__ void mma_tf32(float& d0, float& d1, float& d2, float& d3,
                                         unsigned a0, unsigned a1, unsigned a2, unsigned a3,
                                         unsigned b0, unsigned b1) {
    asm volatile(
        "mma.sync.aligned.m16n8k8.row.col.f32.tf32.tf32.f32 "
        "{%0,%1,%2,%3}, {%4,%5,%6,%7}, {%8,%9}, {%0,%1,%2,%3};\n"
        : "+f"(d0), "+f"(d1), "+f"(d2), "+f"(d3)
        : "r"(a0), "r"(a1), "r"(a2), "r"(a3), "r"(b0), "r"(b1));
}

__global__ __launch_bounds__(128, 4)
void kron_kernel(const float* __restrict__ x,
                 const float* __restrict__ diag_scale,
                 float* __restrict__ out, int ntiles) {
    extern __shared__ float smem[];
    float* sDiag = smem;                       // 4096 fp32
    float* sMR   = smem + 4096;                // 64*SSTR tf32 bits
    float* sXs   = sMR + 64 * SSTR;            // 64*SSTR tf32 bits; T in-place

    int tid  = threadIdx.x;
    int warp = tid >> 5, lane = tid & 31;
    int g = lane >> 2, t4 = lane & 3;
    int strip = warp * 16;                     // this warp's 16 output rows

    for (int i = tid; i < 4096; i += 128) {
        sDiag[i] = diag_scale[i];
        int r = i >> 6, c = i & 63;
        sMR[r * SSTR + c] = __uint_as_float(f2tf(g_MR[i]));
    }
    unsigned a1f[8][4];
#pragma unroll
    for (int kk = 0; kk < 8; ++kk) {
        int i0 = kk * 8 + t4;
        a1f[kk][0] = f2tf(g_ML[(strip + g)     * 64 + i0]);
        a1f[kk][1] = f2tf(g_ML[(strip + g + 8) * 64 + i0]);
        a1f[kk][2] = f2tf(g_ML[(strip + g)     * 64 + i0 + 4]);
        a1f[kk][3] = f2tf(g_ML[(strip + g + 8) * 64 + i0 + 4]);
    }
    __syncthreads();

    int t = blockIdx.x;
    float4 pf[8];
    if (t < ntiles) {
        const float4* xt = (const float4*)(x + (size_t)t * 4096);
#pragma unroll
        for (int it = 0; it < 8; ++it) pf[it] = xt[it * 128 + tid];
    }

    const float4* dg = (const float4*)sDiag;
    while (t < ntiles) {
        // ---- stage Xs = x_tile * diag_scale (tf32 bits) ----
#pragma unroll
        for (int it = 0; it < 8; ++it) {
            int idx = it * 128 + tid;
            float4 v = pf[it];
            float4 s = dg[idx];
            uint4 pk = make_uint4(f2tf(v.x * s.x), f2tf(v.y * s.y),
                                  f2tf(v.z * s.z), f2tf(v.w * s.w));
            int row = idx >> 4, col = (idx & 15) << 2;
            *(uint4*)&sXs[row * SSTR + col] = pk;
        }
        __syncthreads();

        // ---- issue next tile's loads early ----
        int tn = t + NBLK;
        if (tn < ntiles) {
            const float4* xtn = (const float4*)(x + (size_t)tn * 4096);
#pragma unroll
            for (int it = 0; it < 8; ++it) pf[it] = xtn[it * 128 + tid];
        }

        // ---- GEMM1: T_strip = (M_L^T)_strip @ Xs  (kk OUTER: 8 indep chains)
        float c1[8][4];
#pragma unroll
        for (int nn = 0; nn < 8; ++nn) {
            c1[nn][0] = 0.f; c1[nn][1] = 0.f; c1[nn][2] = 0.f; c1[nn][3] = 0.f;
        }
#pragma unroll
        for (int kk = 0; kk < 8; ++kk) {
#pragma unroll
            for (int nn = 0; nn < 8; ++nn) {
                unsigned b0 = __float_as_uint(sXs[(kk * 8 + t4)     * SSTR + nn * 8 + g]);
                unsigned b1 = __float_as_uint(sXs[(kk * 8 + t4 + 4) * SSTR + nn * 8 + g]);
                mma_tf32(c1[nn][0], c1[nn][1], c1[nn][2], c1[nn][3],
                         a1f[kk][0], a1f[kk][1], a1f[kk][2], a1f[kk][3], b0, b1);
            }
        }
        __syncthreads();   // all reads of Xs done -> overwrite with T

        // ---- write T strip in-place ----
#pragma unroll
        for (int nn = 0; nn < 8; ++nn) {
            *(uint2*)&sXs[(strip + g)     * SSTR + nn * 8 + 2 * t4] =
                make_uint2(f2tf(c1[nn][0]), f2tf(c1[nn][1]));
            *(uint2*)&sXs[(strip + g + 8) * SSTR + nn * 8 + 2 * t4] =
                make_uint2(f2tf(c1[nn][2]), f2tf(c1[nn][3]));
        }
        __syncwarp();   // strip is warp-private

        unsigned a2f[8][4];
#pragma unroll
        for (int kk = 0; kk < 8; ++kk) {
            int j0 = kk * 8 + t4;
            a2f[kk][0] = __float_as_uint(sXs[(strip + g)     * SSTR + j0]);
            a2f[kk][1] = __float_as_uint(sXs[(strip + g + 8) * SSTR + j0]);
            a2f[kk][2] = __float_as_uint(sXs[(strip + g)     * SSTR + j0 + 4]);
            a2f[kk][3] = __float_as_uint(sXs[(strip + g + 8) * SSTR + j0 + 4]);
        }

        // ---- GEMM2: O_strip = T_strip @ M_R  (kk OUTER: 8 indep chains)
        float c2[8][4];
#pragma unroll
        for (int nn = 0; nn < 8; ++nn) {
            c2[nn][0] = 0.f; c2[nn][1] = 0.f; c2[nn][2] = 0.f; c2[nn][3] = 0.f;
        }
#pragma unroll
        for (int kk = 0; kk < 8; ++kk) {
#pragma unroll
            for (int nn = 0; nn < 8; ++nn) {
                unsigned b0 = __float_as_uint(sMR[(kk * 8 + t4)     * SSTR + nn * 8 + g]);
                unsigned b1 = __float_as_uint(sMR[(kk * 8 + t4 + 4) * SSTR + nn * 8 + g]);
                mma_tf32(c2[nn][0], c2[nn][1], c2[nn][2], c2[nn][3],
                         a2f[kk][0], a2f[kk][1], a2f[kk][2], a2f[kk][3], b0, b1);
            }
        }

        // ---- coalesced store ----
        float* ot = out + (size_t)t * 4096;
#pragma unroll
        for (int nn = 0; nn < 8; ++nn) {
            int row = strip + g, col = nn * 8 + 2 * t4;
            *(float2*)&ot[row * 64 + col]       = make_float2(c2[nn][0], c2[nn][1]);
            *(float2*)&ot[(row + 8) * 64 + col] = make_float2(c2[nn][2], c2[nn][3]);
        }
        __syncthreads();   // T consumed -> next staging may overwrite
        t = tn;
    }
}

// ---------------- launch ----------------
extern "C" void kernel_launch(void* const* d_in, const int* in_sizes, int n_in,
                              void* d_out, int out_size) {
    const float* x          = (const float*)d_in[0];
    const float* u_left     = (const float*)d_in[1];
    const float* v_left     = (const float*)d_in[2];
    const float* diag_left  = (const float*)d_in[3];
    const float* u_right    = (const float*)d_in[4];
    const float* v_right    = (const float*)d_in[5];
    const float* diag_right = (const float*)d_in[6];
    const float* diag_scale = (const float*)d_in[7];
    float* out = (float*)d_out;

    int ntiles = in_sizes[0] / 4096;

    const int PREP_SMEM = 4 * 64 * PSTR * (int)sizeof(float);            // 69632
    const int KRON_SMEM = (4096 + 2 * 64 * SSTR) * (int)sizeof(float);   // 53248
    cudaFuncSetAttribute(prep_kernel, cudaFuncAttributeMaxDynamicSharedMemorySize, PREP_SMEM);
    cudaFuncSetAttribute(kron_kernel, cudaFuncAttributeMaxDynamicSharedMemorySize, KRON_SMEM);

    reset_kernel<<<1, 1>>>();
    prep_kernel<<<4, 256, PREP_SMEM>>>(u_left, v_left, diag_left,
                                       u_right, v_right, diag_right);
    int grid = ntiles < NBLK ? (ntiles > 0 ? ntiles : 1) : NBLK;
    kron_kernel<<<grid, 128, KRON_SMEM>>>(x, diag_scale, out, ntiles);
}

// round 12
// speedup vs baseline: 1.1647x; 1.1061x over previous
#include <cuda_runtime.h>
#include <cstdint>

// ============================================================
// SVDDecomposeTransMatrix — round 12.
//   prep_kernel: 4 blocks, all-smem Horner Cayley (k<8) + flag-synced
//                compose -> g_ML (transposed), g_MR. Flags self-reset.
//   kron_kernel: round-4 nn-outer core; GEMM2 restructured as
//                O^T = M_R^T @ T^T  (A-frags const in regs, B-frags
//                read T in place)  -> sMR eliminated, -40% crossbar.
// ============================================================

#define PSTR 68   // prep smem stride
#define SSTR 72   // kron smem stride
#define NBLK 456  // 152 SMs * 3

__device__ float g_Qv[2][4096];   // Cayley(v_left), Cayley(v_right)
__device__ float g_ML[4096];      // TRANSPOSED m_left: g_ML[l*64+i] = m_left[i][l]
__device__ float g_MR[4096];      // m_right row-major: g_MR[j*64+r]
__device__ int   g_qdone[2];      // set by blocks 1/3, reset by consumers 0/2

__device__ __forceinline__ int ld_acquire(const int* p) {
    int v; asm volatile("ld.acquire.gpu.b32 %0, [%1];" : "=r"(v) : "l"(p)); return v;
}

// C = A*B (+B if ADD), 64x64 all stride PSTR, 256 threads, 2x8 tiles.
template <bool ADD>
__device__ __forceinline__ void mm256(const float* __restrict__ A,
                                      const float* __restrict__ B,
                                      float* __restrict__ C, int tid) {
    int r0 = (tid >> 3) * 2;
    int c0 = (tid & 7) * 8;
    float a0[8] = {0,0,0,0,0,0,0,0};
    float a1[8] = {0,0,0,0,0,0,0,0};
#pragma unroll 8
    for (int k = 0; k < 64; ++k) {
        float4 bl = *(const float4*)&B[k * PSTR + c0];
        float4 bh = *(const float4*)&B[k * PSTR + c0 + 4];
        float x0 = A[r0 * PSTR + k];
        float x1 = A[(r0 + 1) * PSTR + k];
        a0[0]+=x0*bl.x; a0[1]+=x0*bl.y; a0[2]+=x0*bl.z; a0[3]+=x0*bl.w;
        a0[4]+=x0*bh.x; a0[5]+=x0*bh.y; a0[6]+=x0*bh.z; a0[7]+=x0*bh.w;
        a1[0]+=x1*bl.x; a1[1]+=x1*bl.y; a1[2]+=x1*bl.z; a1[3]+=x1*bl.w;
        a1[4]+=x1*bh.x; a1[5]+=x1*bh.y; a1[6]+=x1*bh.z; a1[7]+=x1*bh.w;
    }
    if (ADD) {
#pragma unroll
        for (int j = 0; j < 8; ++j) {
            a0[j] += B[r0 * PSTR + c0 + j];
            a1[j] += B[(r0 + 1) * PSTR + c0 + j];
        }
    }
    *(float4*)&C[r0 * PSTR + c0]           = make_float4(a0[0],a0[1],a0[2],a0[3]);
    *(float4*)&C[r0 * PSTR + c0 + 4]       = make_float4(a0[4],a0[5],a0[6],a0[7]);
    *(float4*)&C[(r0 + 1) * PSTR + c0]     = make_float4(a1[0],a1[1],a1[2],a1[3]);
    *(float4*)&C[(r0 + 1) * PSTR + c0 + 4] = make_float4(a1[4],a1[5],a1[6],a1[7]);
}

// ---------------- prep: 4 blocks, all-smem Cayley + compose ----------------
// Q = (I+B)(I+B)(I+B^2)(I+B^4), B = A/2 (series k<8, trunc ~4e-7)
__global__ __launch_bounds__(256)
void prep_kernel(const float* __restrict__ u_left,
                 const float* __restrict__ v_left,
                 const float* __restrict__ diag_left,
                 const float* __restrict__ u_right,
                 const float* __restrict__ v_right,
                 const float* __restrict__ diag_right) {
    extern __shared__ float sm[];
    float* B = sm;
    float* P = B + 64 * PSTR;
    float* R = P + 64 * PSTR;
    float* T = R + 64 * PSTR;
    int tid = threadIdx.x, bid = blockIdx.x;
    const float* X = (bid == 0) ? u_left : (bid == 1) ? v_left :
                     (bid == 2) ? u_right : v_right;

    for (int idx = tid; idx < 4096; idx += 256) {
        int i = idx >> 6, j = idx & 63;
        float a = (i > j) ? X[i * 64 + j] : (i < j ? -X[j * 64 + i] : 0.f);
        float b = 0.5f * a;
        B[i * PSTR + j] = b;
        R[i * PSTR + j] = (i == j) ? 1.f + b : b;   // I + B
    }
    __syncthreads();
    mm256<true >(B, R, T, tid);    // T = (I+B)R
    mm256<false>(B, B, P, tid);    // P = B^2
    __syncthreads();
    mm256<true >(P, T, R, tid);    // R = (I+B^2)T
    mm256<false>(P, P, B, tid);    // B <- B^4
    __syncthreads();
    mm256<true >(B, R, T, tid);    // T = Q
    __syncthreads();

    if (bid == 1 || bid == 3) {
        float* dst = g_Qv[bid >> 1];
        for (int idx = tid; idx < 4096; idx += 256) {
            int i = idx >> 6, j = idx & 63;
            dst[idx] = T[i * PSTR + j];
        }
        __threadfence();
        __syncthreads();
        if (tid == 0) atomicExch(&g_qdone[bid >> 1], 1);
    } else {
        if (tid == 0) { while (ld_acquire(&g_qdone[bid >> 1]) == 0) __nanosleep(64); }
        __syncthreads();
        const float* Qv = g_Qv[bid >> 1];
        const float* d  = (bid == 0) ? diag_left : diag_right;
        for (int idx = tid; idx < 4096; idx += 256) {
            int i = idx >> 6, j = idx & 63;
            P[i * PSTR + j] = d[i] * Qv[idx];        // D = diag * Q_v
        }
        __syncthreads();
        mm256<false>(T, P, R, tid);                  // M = Q_u @ D
        __syncthreads();
        for (int idx = tid; idx < 4096; idx += 256) {
            int a = idx >> 6, b = idx & 63;
            float v = R[a * PSTR + b];
            if (bid == 0) g_ML[b * 64 + a] = v;      // m_left transposed
            else          g_MR[a * 64 + b] = v;
        }
        __syncthreads();
        if (tid == 0) atomicExch(&g_qdone[bid >> 1], 0);  // self-reset for next replay
    }
}

// ---------------- main: persistent batched 64x64x64x2 GEMM, TF32 mma -------
__device__ __forceinline__ unsigned f2tf(float f) {
    unsigned u; asm("cvt.rna.tf32.f32 %0, %1;" : "=r"(u) : "f"(f)); return u;
}

__device__ __forceinline__ void mma_tf32(float& d0, float& d1, float& d2, float& d3,
                                         unsigned a0, unsigned a1, unsigned a2, unsigned a3,
                                         unsigned b0, unsigned b1) {
    asm volatile(
        "mma.sync.aligned.m16n8k8.row.col.f32.tf32.tf32.f32 "
        "{%0,%1,%2,%3}, {%4,%5,%6,%7}, {%8,%9}, {%0,%1,%2,%3};\n"
        : "+f"(d0), "+f"(d1), "+f"(d2), "+f"(d3)
        : "r"(a0), "r"(a1), "r"(a2), "r"(a3), "r"(b0), "r"(b1));
}

__global__ __launch_bounds__(128, 3)
void kron_kernel(const float* __restrict__ x,
                 const float* __restrict__ diag_scale,
                 float* __restrict__ out, int ntiles) {
    extern __shared__ float smem[];
    float* sDiag = smem;                       // 4096 fp32
    float* sXs   = smem + 4096;                // 64*SSTR tf32 bits; T in-place

    int tid  = threadIdx.x;
    int warp = tid >> 5, lane = tid & 31;
    int g = lane >> 2, t4 = lane & 3;
    int strip = warp * 16;                     // warp's 16 m-rows (GEMM1: l; GEMM2: r)

    for (int i = tid; i < 4096; i += 128) sDiag[i] = diag_scale[i];

    // GEMM1 A-frags: A = M_L^T (m=l, k=i) = g_ML[m*64+k]
    unsigned a1f[8][4];
#pragma unroll
    for (int kk = 0; kk < 8; ++kk) {
        int i0 = kk * 8 + t4;
        a1f[kk][0] = f2tf(g_ML[(strip + g)     * 64 + i0]);
        a1f[kk][1] = f2tf(g_ML[(strip + g + 8) * 64 + i0]);
        a1f[kk][2] = f2tf(g_ML[(strip + g)     * 64 + i0 + 4]);
        a1f[kk][3] = f2tf(g_ML[(strip + g + 8) * 64 + i0 + 4]);
    }
    // GEMM2 A-frags: A = M_R^T (m=r, k=j) = g_MR[k*64+m]
    unsigned a2c[8][4];
#pragma unroll
    for (int kk = 0; kk < 8; ++kk) {
        int j0 = kk * 8 + t4;
        a2c[kk][0] = f2tf(g_MR[j0       * 64 + strip + g]);
        a2c[kk][1] = f2tf(g_MR[j0       * 64 + strip + g + 8]);
        a2c[kk][2] = f2tf(g_MR[(j0 + 4) * 64 + strip + g]);
        a2c[kk][3] = f2tf(g_MR[(j0 + 4) * 64 + strip + g + 8]);
    }
    __syncthreads();

    int t = blockIdx.x;
    float4 pf[8];
    if (t < ntiles) {
        const float4* xt = (const float4*)(x + (size_t)t * 4096);
#pragma unroll
        for (int it = 0; it < 8; ++it) pf[it] = xt[it * 128 + tid];
    }

    const float4* dg = (const float4*)sDiag;
    while (t < ntiles) {
        // ---- stage Xs = x_tile * diag_scale (tf32 bits) ----
#pragma unroll
        for (int it = 0; it < 8; ++it) {
            int idx = it * 128 + tid;
            float4 v = pf[it];
            float4 s = dg[idx];
            uint4 pk = make_uint4(f2tf(v.x * s.x), f2tf(v.y * s.y),
                                  f2tf(v.z * s.z), f2tf(v.w * s.w));
            int row = idx >> 4, col = (idx & 15) << 2;
            *(uint4*)&sXs[row * SSTR + col] = pk;
        }
        __syncthreads();

        // ---- issue next tile's loads early ----
        int tn = t + NBLK;
        if (tn < ntiles) {
            const float4* xtn = (const float4*)(x + (size_t)tn * 4096);
#pragma unroll
            for (int it = 0; it < 8; ++it) pf[it] = xtn[it * 128 + tid];
        }

        // ---- GEMM1: T_strip[l,j] = (M_L^T)_strip @ Xs  (nn outer, proven) ----
        float c1[8][4];
#pragma unroll
        for (int nn = 0; nn < 8; ++nn) {
            c1[nn][0] = 0.f; c1[nn][1] = 0.f; c1[nn][2] = 0.f; c1[nn][3] = 0.f;
#pragma unroll
            for (int kk = 0; kk < 8; ++kk) {
                unsigned b0 = __float_as_uint(sXs[(kk * 8 + t4)     * SSTR + nn * 8 + g]);
                unsigned b1 = __float_as_uint(sXs[(kk * 8 + t4 + 4) * SSTR + nn * 8 + g]);
                mma_tf32(c1[nn][0], c1[nn][1], c1[nn][2], c1[nn][3],
                         a1f[kk][0], a1f[kk][1], a1f[kk][2], a1f[kk][3], b0, b1);
            }
        }
        __syncthreads();   // all reads of Xs done -> overwrite with T

        // ---- write T[l,j] in-place (rows l = strip..strip+15) ----
#pragma unroll
        for (int nn = 0; nn < 8; ++nn) {
            *(uint2*)&sXs[(strip + g)     * SSTR + nn * 8 + 2 * t4] =
                make_uint2(f2tf(c1[nn][0]), f2tf(c1[nn][1]));
            *(uint2*)&sXs[(strip + g + 8) * SSTR + nn * 8 + 2 * t4] =
                make_uint2(f2tf(c1[nn][2]), f2tf(c1[nn][3]));
        }
        __syncthreads();   // T is read cross-warp in GEMM2

        // ---- GEMM2: O^T[r,l] = (M_R^T)_strip @ T^T ----
        // B-frag[k=j, n=l] = T[l, j] read in T's native layout.
        float* ot = out + (size_t)t * 4096;
#pragma unroll
        for (int nn = 0; nn < 8; ++nn) {
            float c0 = 0.f, c1v = 0.f, c2 = 0.f, c3 = 0.f;
#pragma unroll
            for (int kk = 0; kk < 8; ++kk) {
                unsigned b0 = __float_as_uint(sXs[(nn * 8 + g) * SSTR + kk * 8 + t4]);
                unsigned b1 = __float_as_uint(sXs[(nn * 8 + g) * SSTR + kk * 8 + t4 + 4]);
                mma_tf32(c0, c1v, c2, c3,
                         a2c[kk][0], a2c[kk][1], a2c[kk][2], a2c[kk][3], b0, b1);
            }
            // D[m=r, n=l] -> out[l*64 + r]  (32B-sector-complete stores)
            int r = strip + g;
            int l0 = nn * 8 + 2 * t4;
            ot[l0 * 64 + r]           = c0;
            ot[(l0 + 1) * 64 + r]     = c1v;
            ot[l0 * 64 + r + 8]       = c2;
            ot[(l0 + 1) * 64 + r + 8] = c3;
        }
        __syncthreads();   // T consumed -> next staging may overwrite
        t = tn;
    }
}

// ---------------- launch ----------------
extern "C" void kernel_launch(void* const* d_in, const int* in_sizes, int n_in,
                              void* d_out, int out_size) {
    const float* x          = (const float*)d_in[0];
    const float* u_left     = (const float*)d_in[1];
    const float* v_left     = (const float*)d_in[2];
    const float* diag_left  = (const float*)d_in[3];
    const float* u_right    = (const float*)d_in[4];
    const float* v_right    = (const float*)d_in[5];
    const float* diag_right = (const float*)d_in[6];
    const float* diag_scale = (const float*)d_in[7];
    float* out = (float*)d_out;

    int ntiles = in_sizes[0] / 4096;

    const int PREP_SMEM = 4 * 64 * PSTR * (int)sizeof(float);          // 69632
    const int KRON_SMEM = (4096 + 64 * SSTR) * (int)sizeof(float);     // 34816
    cudaFuncSetAttribute(prep_kernel, cudaFuncAttributeMaxDynamicSharedMemorySize, PREP_SMEM);
    cudaFuncSetAttribute(kron_kernel, cudaFuncAttributeMaxDynamicSharedMemorySize, KRON_SMEM);

    prep_kernel<<<4, 256, PREP_SMEM>>>(u_left, v_left, diag_left,
                                       u_right, v_right, diag_right);
    int grid = ntiles < NBLK ? (ntiles > 0 ? ntiles : 1) : NBLK;
    kron_kernel<<<grid, 128, KRON_SMEM>>>(x, diag_scale, out, ntiles);
}

// round 13
// speedup vs baseline: 1.1990x; 1.0295x over previous
#include <cuda_runtime.h>
#include <cstdint>

// ============================================================
// SVDDecomposeTransMatrix — round 13: single fused kernel.
//   Phase 1: blocks 0-3 all-smem Horner Cayley (k<8, 3 buffers)
//            + compose -> g_ML (transposed), g_MR; others L2-prefetch x.
//   Phase 2: round-12 kron core (nn-outer, GEMM2 as O^T = MR^T @ T^T)
//            fed by a dynamic tile queue (leader atomicAdd + broadcast).
//   All flags reset in-kernel -> graph-replay deterministic.
// ============================================================

#define PSTR 68   // prep smem stride
#define SSTR 72   // kron smem stride
#define NBLK 456  // 152 SMs * 3 CTAs -> all resident (spins are safe)

__device__ float g_Qv[2][4096];   // Cayley(v_left), Cayley(v_right)
__device__ float g_ML[4096];      // TRANSPOSED m_left: g_ML[l*64+i] = m_left[i][l]
__device__ float g_MR[4096];      // m_right row-major: g_MR[j*64+r]
__device__ int   g_qdone[2];      // set by blocks 1/3, reset by consumers 0/2
__device__ int   g_mdone;         // compose count; reset by last barrier-passer
__device__ int   g_passed;        // barrier-passer count; reset by last passer
__device__ unsigned g_work;       // tile queue; reset by block 0 in phase 1

__device__ __forceinline__ int ld_acquire(const int* p) {
    int v; asm volatile("ld.acquire.gpu.b32 %0, [%1];" : "=r"(v) : "l"(p)); return v;
}
__device__ __forceinline__ int ld_relaxed(const int* p) {
    int v; asm volatile("ld.relaxed.gpu.b32 %0, [%1];" : "=r"(v) : "l"(p)); return v;
}

// C = A*B (+B if ADD), 64x64 all stride PSTR, 128 threads, 4x8 tiles.
template <bool ADD>
__device__ __forceinline__ void mm128(const float* __restrict__ A,
                                      const float* __restrict__ B,
                                      float* __restrict__ C, int tid) {
    int r0 = (tid >> 3) * 4;
    int c0 = (tid & 7) * 8;
    float acc[4][8];
#pragma unroll
    for (int i = 0; i < 4; ++i)
#pragma unroll
        for (int j = 0; j < 8; ++j) acc[i][j] = 0.f;
#pragma unroll 4
    for (int k = 0; k < 64; ++k) {
        float4 bl = *(const float4*)&B[k * PSTR + c0];
        float4 bh = *(const float4*)&B[k * PSTR + c0 + 4];
        float bv[8] = {bl.x, bl.y, bl.z, bl.w, bh.x, bh.y, bh.z, bh.w};
#pragma unroll
        for (int i = 0; i < 4; ++i) {
            float a = A[(r0 + i) * PSTR + k];
#pragma unroll
            for (int j = 0; j < 8; ++j) acc[i][j] += a * bv[j];
        }
    }
#pragma unroll
    for (int i = 0; i < 4; ++i) {
        if (ADD) {
#pragma unroll
            for (int j = 0; j < 8; ++j) acc[i][j] += B[(r0 + i) * PSTR + c0 + j];
        }
        *(float4*)&C[(r0 + i) * PSTR + c0]     = make_float4(acc[i][0], acc[i][1], acc[i][2], acc[i][3]);
        *(float4*)&C[(r0 + i) * PSTR + c0 + 4] = make_float4(acc[i][4], acc[i][5], acc[i][6], acc[i][7]);
    }
}

__device__ __forceinline__ unsigned f2tf(float f) {
    unsigned u; asm("cvt.rna.tf32.f32 %0, %1;" : "=r"(u) : "f"(f)); return u;
}

__device__ __forceinline__ void mma_tf32(float& d0, float& d1, float& d2, float& d3,
                                         unsigned a0, unsigned a1, unsigned a2, unsigned a3,
                                         unsigned b0, unsigned b1) {
    asm volatile(
        "mma.sync.aligned.m16n8k8.row.col.f32.tf32.tf32.f32 "
        "{%0,%1,%2,%3}, {%4,%5,%6,%7}, {%8,%9}, {%0,%1,%2,%3};\n"
        : "+f"(d0), "+f"(d1), "+f"(d2), "+f"(d3)
        : "r"(a0), "r"(a1), "r"(a2), "r"(a3), "r"(b0), "r"(b1));
}

__global__ __launch_bounds__(128, 3)
void fused_kernel(const float* __restrict__ x,
                  const float* __restrict__ u_left,
                  const float* __restrict__ v_left,
                  const float* __restrict__ diag_left,
                  const float* __restrict__ u_right,
                  const float* __restrict__ v_right,
                  const float* __restrict__ diag_right,
                  const float* __restrict__ diag_scale,
                  float* __restrict__ out, int ntiles) {
    extern __shared__ float sm[];
    __shared__ unsigned sp;
    int tid = threadIdx.x, bid = blockIdx.x;

    // ========== PHASE 1: prep (blocks 0-3) / L2 prefetch (others) ==========
    if (bid < 4) {
        // 3-buffer Horner: Q = (I+B)(I+B)(I+B^2)(I+B^4), B = A/2 (k<8)
        float* s0 = sm;                  // starts = B
        float* s1 = s0 + 64 * PSTR;      // starts = I+B
        float* s2 = s1 + 64 * PSTR;
        const float* X = (bid == 0) ? u_left : (bid == 1) ? v_left :
                         (bid == 2) ? u_right : v_right;
        for (int idx = tid; idx < 4096; idx += 128) {
            int i = idx >> 6, j = idx & 63;
            float a = (i > j) ? X[i * 64 + j] : (i < j ? -X[j * 64 + i] : 0.f);
            float b = 0.5f * a;
            s0[i * PSTR + j] = b;
            s1[i * PSTR + j] = (i == j) ? 1.f + b : b;
        }
        __syncthreads();
        mm128<true >(s0, s1, s2, tid);   // s2 = (I+B)(I+B)
        __syncthreads();                 // s1 free after reads
        mm128<false>(s0, s0, s1, tid);   // s1 = B^2
        __syncthreads();
        mm128<true >(s1, s2, s0, tid);   // s0 = (I+B^2)s2   (B no longer needed)
        __syncthreads();
        mm128<false>(s1, s1, s2, tid);   // s2 = B^4
        __syncthreads();
        mm128<true >(s2, s0, s1, tid);   // s1 = Q = (I+B^4)s0
        __syncthreads();

        if (bid == 1 || bid == 3) {
            float* dst = g_Qv[bid >> 1];
            for (int idx = tid; idx < 4096; idx += 128) {
                int i = idx >> 6, j = idx & 63;
                dst[idx] = s1[i * PSTR + j];
            }
            __threadfence();
            __syncthreads();
            if (tid == 0) atomicExch(&g_qdone[bid >> 1], 1);
        } else {
            if (tid == 0) { while (ld_acquire(&g_qdone[bid >> 1]) == 0) __nanosleep(64); }
            __syncthreads();
            const float* Qv = g_Qv[bid >> 1];
            const float* d  = (bid == 0) ? diag_left : diag_right;
            for (int idx = tid; idx < 4096; idx += 128) {
                int i = idx >> 6, j = idx & 63;
                s2[i * PSTR + j] = d[i] * Qv[idx];    // D = diag * Q_v
            }
            __syncthreads();
            mm128<false>(s1, s2, s0, tid);            // M = Q_u @ D  -> s0
            __syncthreads();
            for (int idx = tid; idx < 4096; idx += 128) {
                int a = idx >> 6, b = idx & 63;
                float v = s0[a * PSTR + b];
                if (bid == 0) g_ML[b * 64 + a] = v;   // m_left transposed
                else          g_MR[a * 64 + b] = v;
            }
            __syncthreads();
            if (tid == 0) {
                atomicExch(&g_qdone[bid >> 1], 0);    // self-reset for next replay
                if (bid == 0) g_work = 0;             // queue reset, ordered by fence below
                __threadfence();
                atomicAdd(&g_mdone, 1);
            }
        }
    } else {
        // warm L2 with x while prep runs
        const char* xb = (const char*)x;
        for (int q = bid; q < ntiles; q += NBLK) {
            if (ld_relaxed(&g_mdone) >= 2) break;
            const char* pc = xb + (size_t)q * 16384 + tid * 128;
            asm volatile("prefetch.global.L2 [%0];" :: "l"(pc));
        }
    }

    // ========== barrier on prep completion (+ flag recycling) ==========
    if (tid == 0) {
        while (ld_acquire(&g_mdone) < 2) __nanosleep(32);
        int old = atomicAdd(&g_passed, 1);
        if (old == NBLK - 1) {            // everyone has passed -> safe to recycle
            atomicExch(&g_mdone, 0);
            atomicExch(&g_passed, 0);
        }
    }
    __syncthreads();

    // ========== PHASE 2: round-12 kron core + dynamic queue ==========
    float* sDiag = sm;                       // 4096 fp32
    float* sXs   = sm + 4096;                // 64*SSTR tf32 bits; T in-place

    int warp = tid >> 5, lane = tid & 31;
    int g = lane >> 2, t4 = lane & 3;
    int strip = warp * 16;

    for (int i = tid; i < 4096; i += 128) sDiag[i] = diag_scale[i];

    // GEMM1 A-frags: A = M_L^T (m=l, k=i) = g_ML[m*64+k]
    unsigned a1f[8][4];
#pragma unroll
    for (int kk = 0; kk < 8; ++kk) {
        int i0 = kk * 8 + t4;
        a1f[kk][0] = f2tf(g_ML[(strip + g)     * 64 + i0]);
        a1f[kk][1] = f2tf(g_ML[(strip + g + 8) * 64 + i0]);
        a1f[kk][2] = f2tf(g_ML[(strip + g)     * 64 + i0 + 4]);
        a1f[kk][3] = f2tf(g_ML[(strip + g + 8) * 64 + i0 + 4]);
    }
    // GEMM2 A-frags: A = M_R^T (m=r, k=j) = g_MR[k*64+m]
    unsigned a2c[8][4];
#pragma unroll
    for (int kk = 0; kk < 8; ++kk) {
        int j0 = kk * 8 + t4;
        a2c[kk][0] = f2tf(g_MR[j0       * 64 + strip + g]);
        a2c[kk][1] = f2tf(g_MR[j0       * 64 + strip + g + 8]);
        a2c[kk][2] = f2tf(g_MR[(j0 + 4) * 64 + strip + g]);
        a2c[kk][3] = f2tf(g_MR[(j0 + 4) * 64 + strip + g + 8]);
    }
    if (tid == 0) sp = atomicAdd(&g_work, 1u);
    __syncthreads();                         // constants staged + sp visible

    int t = (int)sp;
    float4 pf[8];
    if (t < ntiles) {
        const float4* xt = (const float4*)(x + (size_t)t * 4096);
#pragma unroll
        for (int it = 0; it < 8; ++it) pf[it] = xt[it * 128 + tid];
    }

    const float4* dg = (const float4*)sDiag;
    while (t < ntiles) {
        // ---- stage Xs = x_tile * diag_scale (tf32 bits) ----
#pragma unroll
        for (int it = 0; it < 8; ++it) {
            int idx = it * 128 + tid;
            float4 v = pf[it];
            float4 s = dg[idx];
            uint4 pk = make_uint4(f2tf(v.x * s.x), f2tf(v.y * s.y),
                                  f2tf(v.z * s.z), f2tf(v.w * s.w));
            int row = idx >> 4, col = (idx & 15) << 2;
            *(uint4*)&sXs[row * SSTR + col] = pk;
        }
        if (tid == 0) sp = atomicAdd(&g_work, 1u);   // leader grabs next tile
        __syncthreads();                             // staging done + sp visible
        int tn = (int)sp;

        // ---- issue next tile's loads early ----
        if (tn < ntiles) {
            const float4* xtn = (const float4*)(x + (size_t)tn * 4096);
#pragma unroll
            for (int it = 0; it < 8; ++it) pf[it] = xtn[it * 128 + tid];
        }

        // ---- GEMM1: T_strip[l,j] = (M_L^T)_strip @ Xs (nn outer) ----
        float c1[8][4];
#pragma unroll
        for (int nn = 0; nn < 8; ++nn) {
            c1[nn][0] = 0.f; c1[nn][1] = 0.f; c1[nn][2] = 0.f; c1[nn][3] = 0.f;
#pragma unroll
            for (int kk = 0; kk < 8; ++kk) {
                unsigned b0 = __float_as_uint(sXs[(kk * 8 + t4)     * SSTR + nn * 8 + g]);
                unsigned b1 = __float_as_uint(sXs[(kk * 8 + t4 + 4) * SSTR + nn * 8 + g]);
                mma_tf32(c1[nn][0], c1[nn][1], c1[nn][2], c1[nn][3],
                         a1f[kk][0], a1f[kk][1], a1f[kk][2], a1f[kk][3], b0, b1);
            }
        }
        __syncthreads();   // all reads of Xs done -> overwrite with T

        // ---- write T[l,j] in-place ----
#pragma unroll
        for (int nn = 0; nn < 8; ++nn) {
            *(uint2*)&sXs[(strip + g)     * SSTR + nn * 8 + 2 * t4] =
                make_uint2(f2tf(c1[nn][0]), f2tf(c1[nn][1]));
            *(uint2*)&sXs[(strip + g + 8) * SSTR + nn * 8 + 2 * t4] =
                make_uint2(f2tf(c1[nn][2]), f2tf(c1[nn][3]));
        }
        __syncthreads();   // T read cross-warp in GEMM2

        // ---- GEMM2: O^T[r,l] = (M_R^T)_strip @ T^T ----
        float* ot = out + (size_t)t * 4096;
#pragma unroll
        for (int nn = 0; nn < 8; ++nn) {
            float c0 = 0.f, c1v = 0.f, c2 = 0.f, c3 = 0.f;
#pragma unroll
            for (int kk = 0; kk < 8; ++kk) {
                unsigned b0 = __float_as_uint(sXs[(nn * 8 + g) * SSTR + kk * 8 + t4]);
                unsigned b1 = __float_as_uint(sXs[(nn * 8 + g) * SSTR + kk * 8 + t4 + 4]);
                mma_tf32(c0, c1v, c2, c3,
                         a2c[kk][0], a2c[kk][1], a2c[kk][2], a2c[kk][3], b0, b1);
            }
            int r = strip + g;
            int l0 = nn * 8 + 2 * t4;
            ot[l0 * 64 + r]           = c0;
            ot[(l0 + 1) * 64 + r]     = c1v;
            ot[l0 * 64 + r + 8]       = c2;
            ot[(l0 + 1) * 64 + r + 8] = c3;
        }
        __syncthreads();   // T consumed -> next staging may overwrite
        t = tn;
    }
}

// ---------------- launch ----------------
extern "C" void kernel_launch(void* const* d_in, const int* in_sizes, int n_in,
                              void* d_out, int out_size) {
    const float* x          = (const float*)d_in[0];
    const float* u_left     = (const float*)d_in[1];
    const float* v_left     = (const float*)d_in[2];
    const float* diag_left  = (const float*)d_in[3];
    const float* u_right    = (const float*)d_in[4];
    const float* v_right    = (const float*)d_in[5];
    const float* diag_right = (const float*)d_in[6];
    const float* diag_scale = (const float*)d_in[7];
    float* out = (float*)d_out;

    int ntiles = in_sizes[0] / 4096;

    // smem = max(prep 3*64*68, kron 4096 + 64*72) = 13056 floats = 52224 B
    const int SMEM_BYTES = 3 * 64 * PSTR * (int)sizeof(float);
    cudaFuncSetAttribute(fused_kernel, cudaFuncAttributeMaxDynamicSharedMemorySize, SMEM_BYTES);

    fused_kernel<<<NBLK, 128, SMEM_BYTES>>>(x, u_left, v_left, diag_left,
                                            u_right, v_right, diag_right,
                                            diag_scale, out, ntiles);
}

// round 15
// speedup vs baseline: 1.2445x; 1.0380x over previous
#include <cuda_runtime.h>
#include <cstdint>

// ============================================================
// SVDDecomposeTransMatrix — round 14: single fused kernel.
//   Phase 1: blocks 0-3 all-smem Horner Cayley (k<8) + compose
//            -> g_ML (transposed), g_MR; others L2-prefetch x.
//   Phase 2: nn-outer TF32 mma kron; GEMM2 as O^T = MR^T @ T^T with
//            dedicated T buffer @stride 68 (conflict-free B reads),
//            double-buffered Xs -> only 2 barriers per tile.
// ============================================================

#define PSTR 68   // prep smem stride
#define SSTR 72   // Xs smem stride (conflict-free GEMM1 B reads)
#define TSTR 68   // T  smem stride (conflict-free GEMM2 B reads)
#define NBLK 456  // 152 SMs * 3 CTAs -> all resident (spins are safe)

__device__ float g_Qv[2][4096];   // Cayley(v_left), Cayley(v_right)
__device__ float g_ML[4096];      // TRANSPOSED m_left: g_ML[l*64+i] = m_left[i][l]
__device__ float g_MR[4096];      // m_right row-major: g_MR[j*64+r]
__device__ int   g_qdone[2];      // set by blocks 1/3, reset by consumers 0/2
__device__ int   g_mdone;         // compose count; reset by last barrier-passer
__device__ int   g_passed;        // barrier-passer count; reset by last passer
__device__ unsigned g_work;       // tile queue; reset by block 0 in phase 1

__device__ __forceinline__ int ld_acquire(const int* p) {
    int v; asm volatile("ld.acquire.gpu.b32 %0, [%1];" : "=r"(v) : "l"(p)); return v;
}
__device__ __forceinline__ int ld_relaxed(const int* p) {
    int v; asm volatile("ld.relaxed.gpu.b32 %0, [%1];" : "=r"(v) : "l"(p)); return v;
}

// C = A*B (+B if ADD), 64x64 all stride PSTR, 128 threads, 4x8 tiles.
template <bool ADD>
__device__ __forceinline__ void mm128(const float* __restrict__ A,
                                      const float* __restrict__ B,
                                      float* __restrict__ C, int tid) {
    int r0 = (tid >> 3) * 4;
    int c0 = (tid & 7) * 8;
    float acc[4][8];
#pragma unroll
    for (int i = 0; i < 4; ++i)
#pragma unroll
        for (int j = 0; j < 8; ++j) acc[i][j] = 0.f;
#pragma unroll 4
    for (int k = 0; k < 64; ++k) {
        float4 bl = *(const float4*)&B[k * PSTR + c0];
        float4 bh = *(const float4*)&B[k * PSTR + c0 + 4];
        float bv[8] = {bl.x, bl.y, bl.z, bl.w, bh.x, bh.y, bh.z, bh.w};
#pragma unroll
        for (int i = 0; i < 4; ++i) {
            float a = A[(r0 + i) * PSTR + k];
#pragma unroll
            for (int j = 0; j < 8; ++j) acc[i][j] += a * bv[j];
        }
    }
#pragma unroll
    for (int i = 0; i < 4; ++i) {
        if (ADD) {
#pragma unroll
            for (int j = 0; j < 8; ++j) acc[i][j] += B[(r0 + i) * PSTR + c0 + j];
        }
        *(float4*)&C[(r0 + i) * PSTR + c0]     = make_float4(acc[i][0], acc[i][1], acc[i][2], acc[i][3]);
        *(float4*)&C[(r0 + i) * PSTR + c0 + 4] = make_float4(acc[i][4], acc[i][5], acc[i][6], acc[i][7]);
    }
}

__device__ __forceinline__ unsigned f2tf(float f) {
    unsigned u; asm("cvt.rna.tf32.f32 %0, %1;" : "=r"(u) : "f"(f)); return u;
}

__device__ __forceinline__ void mma_tf32(float& d0, float& d1, float& d2, float& d3,
                                         unsigned a0, unsigned a1, unsigned a2, unsigned a3,
                                         unsigned b0, unsigned b1) {
    asm volatile(
        "mma.sync.aligned.m16n8k8.row.col.f32.tf32.tf32.f32 "
        "{%0,%1,%2,%3}, {%4,%5,%6,%7}, {%8,%9}, {%0,%1,%2,%3};\n"
        : "+f"(d0), "+f"(d1), "+f"(d2), "+f"(d3)
        : "r"(a0), "r"(a1), "r"(a2), "r"(a3), "r"(b0), "r"(b1));
}

__global__ __launch_bounds__(128, 3)
void fused_kernel(const float* __restrict__ x,
                  const float* __restrict__ u_left,
                  const float* __restrict__ v_left,
                  const float* __restrict__ diag_left,
                  const float* __restrict__ u_right,
                  const float* __restrict__ v_right,
                  const float* __restrict__ diag_right,
                  const float* __restrict__ diag_scale,
                  float* __restrict__ out, int ntiles) {
    extern __shared__ float sm[];
    __shared__ unsigned sp;
    int tid = threadIdx.x, bid = blockIdx.x;

    // ========== PHASE 1: prep (blocks 0-3) / L2 prefetch (others) ==========
    if (bid < 4) {
        // 3-buffer Horner: Q = (I+B)(I+B)(I+B^2)(I+B^4), B = A/2 (k<8)
        float* s0 = sm;                  // starts = B
        float* s1 = s0 + 64 * PSTR;      // starts = I+B
        float* s2 = s1 + 64 * PSTR;
        const float* X = (bid == 0) ? u_left : (bid == 1) ? v_left :
                         (bid == 2) ? u_right : v_right;
        for (int idx = tid; idx < 4096; idx += 128) {
            int i = idx >> 6, j = idx & 63;
            float a = (i > j) ? X[i * 64 + j] : (i < j ? -X[j * 64 + i] : 0.f);
            float b = 0.5f * a;
            s0[i * PSTR + j] = b;
            s1[i * PSTR + j] = (i == j) ? 1.f + b : b;
        }
        __syncthreads();
        mm128<true >(s0, s1, s2, tid);   // s2 = (I+B)(I+B)
        __syncthreads();
        mm128<false>(s0, s0, s1, tid);   // s1 = B^2
        __syncthreads();
        mm128<true >(s1, s2, s0, tid);   // s0 = (I+B^2)s2
        __syncthreads();
        mm128<false>(s1, s1, s2, tid);   // s2 = B^4
        __syncthreads();
        mm128<true >(s2, s0, s1, tid);   // s1 = Q = (I+B^4)s0
        __syncthreads();

        if (bid == 1 || bid == 3) {
            float* dst = g_Qv[bid >> 1];
            for (int idx = tid; idx < 4096; idx += 128) {
                int i = idx >> 6, j = idx & 63;
                dst[idx] = s1[i * PSTR + j];
            }
            __threadfence();
            __syncthreads();
            if (tid == 0) atomicExch(&g_qdone[bid >> 1], 1);
        } else {
            if (tid == 0) { while (ld_acquire(&g_qdone[bid >> 1]) == 0) __nanosleep(64); }
            __syncthreads();
            const float* Qv = g_Qv[bid >> 1];
            const float* d  = (bid == 0) ? diag_left : diag_right;
            for (int idx = tid; idx < 4096; idx += 128) {
                int i = idx >> 6, j = idx & 63;
                s2[i * PSTR + j] = d[i] * Qv[idx];    // D = diag * Q_v
            }
            __syncthreads();
            mm128<false>(s1, s2, s0, tid);            // M = Q_u @ D  -> s0
            __syncthreads();
            for (int idx = tid; idx < 4096; idx += 128) {
                int a = idx >> 6, b = idx & 63;
                float v = s0[a * PSTR + b];
                if (bid == 0) g_ML[b * 64 + a] = v;   // m_left transposed
                else          g_MR[a * 64 + b] = v;
            }
            __syncthreads();
            if (tid == 0) {
                atomicExch(&g_qdone[bid >> 1], 0);    // self-reset for next replay
                if (bid == 0) g_work = 0;             // queue reset before release
                __threadfence();
                atomicAdd(&g_mdone, 1);
            }
        }
    } else {
        // warm L2 with x while prep runs
        const char* xb = (const char*)x;
        for (int q = bid; q < ntiles; q += NBLK) {
            if (ld_relaxed(&g_mdone) >= 2) break;
            const char* pc = xb + (size_t)q * 16384 + tid * 128;
            asm volatile("prefetch.global.L2 [%0];" :: "l"(pc));
        }
    }

    // ========== barrier on prep completion (+ flag recycling) ==========
    if (tid == 0) {
        while (ld_acquire(&g_mdone) < 2) __nanosleep(32);
        int old = atomicAdd(&g_passed, 1);
        if (old == NBLK - 1) {            // all passed -> safe to recycle
            atomicExch(&g_mdone, 0);
            atomicExch(&g_passed, 0);
        }
    }
    __syncthreads();

    // ========== PHASE 2: kron core, double-buffered Xs + dedicated T ==========
    float* sDiag = sm;                       // 4096 fp32
    float* sX0   = sm + 4096;                // 64*SSTR
    float* sX1   = sX0 + 64 * SSTR;          // 64*SSTR
    float* sT    = sX1 + 64 * SSTR;          // 64*TSTR

    int warp = tid >> 5, lane = tid & 31;
    int g = lane >> 2, t4 = lane & 3;
    int strip = warp * 16;

    for (int i = tid; i < 4096; i += 128) sDiag[i] = diag_scale[i];

    // GEMM1 A-frags: A = M_L^T (m=l, k=i) = g_ML[m*64+k]
    unsigned a1f[8][4];
#pragma unroll
    for (int kk = 0; kk < 8; ++kk) {
        int i0 = kk * 8 + t4;
        a1f[kk][0] = f2tf(g_ML[(strip + g)     * 64 + i0]);
        a1f[kk][1] = f2tf(g_ML[(strip + g + 8) * 64 + i0]);
        a1f[kk][2] = f2tf(g_ML[(strip + g)     * 64 + i0 + 4]);
        a1f[kk][3] = f2tf(g_ML[(strip + g + 8) * 64 + i0 + 4]);
    }
    // GEMM2 A-frags: A = M_R^T (m=r, k=j) = g_MR[k*64+m]
    unsigned a2c[8][4];
#pragma unroll
    for (int kk = 0; kk < 8; ++kk) {
        int j0 = kk * 8 + t4;
        a2c[kk][0] = f2tf(g_MR[j0       * 64 + strip + g]);
        a2c[kk][1] = f2tf(g_MR[j0       * 64 + strip + g + 8]);
        a2c[kk][2] = f2tf(g_MR[(j0 + 4) * 64 + strip + g]);
        a2c[kk][3] = f2tf(g_MR[(j0 + 4) * 64 + strip + g + 8]);
    }
    if (tid == 0) sp = atomicAdd(&g_work, 1u);
    __syncthreads();                         // constants staged + sp visible

    int t = (int)sp, cur = 0;
    float4 pf[8];
    if (t < ntiles) {
        const float4* xt = (const float4*)(x + (size_t)t * 4096);
#pragma unroll
        for (int it = 0; it < 8; ++it) pf[it] = xt[it * 128 + tid];
    }

    const float4* dg = (const float4*)sDiag;
    while (t < ntiles) {
        float* sXs = cur ? sX1 : sX0;
        // ---- stage Xs = x_tile * diag_scale (tf32 bits) into current buffer ----
#pragma unroll
        for (int it = 0; it < 8; ++it) {
            int idx = it * 128 + tid;
            float4 v = pf[it];
            float4 s = dg[idx];
            uint4 pk = make_uint4(f2tf(v.x * s.x), f2tf(v.y * s.y),
                                  f2tf(v.z * s.z), f2tf(v.w * s.w));
            int row = idx >> 4, col = (idx & 15) << 2;
            *(uint4*)&sXs[row * SSTR + col] = pk;
        }
        if (tid == 0) sp = atomicAdd(&g_work, 1u);   // leader grabs next tile
        __syncthreads();   // SYNC1: staging + sp visible; also: everyone has
                           // finished GEMM2 of previous tile -> T rewrite safe
        int tn = (int)sp;

        // ---- issue next tile's loads early ----
        if (tn < ntiles) {
            const float4* xtn = (const float4*)(x + (size_t)tn * 4096);
#pragma unroll
            for (int it = 0; it < 8; ++it) pf[it] = xtn[it * 128 + tid];
        }

        // ---- GEMM1: T_strip[l,j] = (M_L^T)_strip @ Xs (nn outer) ----
        float c1[8][4];
#pragma unroll
        for (int nn = 0; nn < 8; ++nn) {
            c1[nn][0] = 0.f; c1[nn][1] = 0.f; c1[nn][2] = 0.f; c1[nn][3] = 0.f;
#pragma unroll
            for (int kk = 0; kk < 8; ++kk) {
                unsigned b0 = __float_as_uint(sXs[(kk * 8 + t4)     * SSTR + nn * 8 + g]);
                unsigned b1 = __float_as_uint(sXs[(kk * 8 + t4 + 4) * SSTR + nn * 8 + g]);
                mma_tf32(c1[nn][0], c1[nn][1], c1[nn][2], c1[nn][3],
                         a1f[kk][0], a1f[kk][1], a1f[kk][2], a1f[kk][3], b0, b1);
            }
        }

        // ---- write T[l,j] into dedicated buffer (stride TSTR) ----
#pragma unroll
        for (int nn = 0; nn < 8; ++nn) {
            *(uint2*)&sT[(strip + g)     * TSTR + nn * 8 + 2 * t4] =
                make_uint2(f2tf(c1[nn][0]), f2tf(c1[nn][1]));
            *(uint2*)&sT[(strip + g + 8) * TSTR + nn * 8 + 2 * t4] =
                make_uint2(f2tf(c1[nn][2]), f2tf(c1[nn][3]));
        }
        __syncthreads();   // SYNC2: T visible to all warps

        // ---- GEMM2: O^T[r,l] = (M_R^T)_strip @ T^T (conflict-free T reads) ----
        float* ot = out + (size_t)t * 4096;
#pragma unroll
        for (int nn = 0; nn < 8; ++nn) {
            float c0 = 0.f, c1v = 0.f, c2 = 0.f, c3 = 0.f;
#pragma unroll
            for (int kk = 0; kk < 8; ++kk) {
                unsigned b0 = __float_as_uint(sT[(nn * 8 + g) * TSTR + kk * 8 + t4]);
                unsigned b1 = __float_as_uint(sT[(nn * 8 + g) * TSTR + kk * 8 + t4 + 4]);
                mma_tf32(c0, c1v, c2, c3,
                         a2c[kk][0], a2c[kk][1], a2c[kk][2], a2c[kk][3], b0, b1);
            }
            int r = strip + g;
            int l0 = nn * 8 + 2 * t4;
            ot[l0 * 64 + r]           = c0;
            ot[(l0 + 1) * 64 + r]     = c1v;
            ot[l0 * 64 + r + 8]       = c2;
            ot[(l0 + 1) * 64 + r + 8] = c3;
        }
        // no tail barrier: next SYNC1 orders GEMM2 completion vs T rewrite,
        // and staging goes to the other X buffer.
        t = tn; cur ^= 1;
    }
}

// ---------------- launch ----------------
extern "C" void kernel_launch(void* const* d_in, const int* in_sizes, int n_in,
                              void* d_out, int out_size) {
    const float* x          = (const float*)d_in[0];
    const float* u_left     = (const float*)d_in[1];
    const float* v_left     = (const float*)d_in[2];
    const float* diag_left  = (const float*)d_in[3];
    const float* u_right    = (const float*)d_in[4];
    const float* v_right    = (const float*)d_in[5];
    const float* diag_right = (const float*)d_in[6];
    const float* diag_scale = (const float*)d_in[7];
    float* out = (float*)d_out;

    int ntiles = in_sizes[0] / 4096;

    // smem = max(prep 3*64*68, kron 4096 + 2*64*72 + 64*68) floats
    //      = max(13056, 17664) = 17664 floats = 70656 B; x3 CTAs = 212KB OK
    const int SMEM_BYTES = (4096 + 2 * 64 * SSTR + 64 * TSTR) * (int)sizeof(float);
    cudaFuncSetAttribute(fused_kernel, cudaFuncAttributeMaxDynamicSharedMemorySize, SMEM_BYTES);

    fused_kernel<<<NBLK, 128, SMEM_BYTES>>>(x, u_left, v_left, diag_left,
                                            u_right, v_right, diag_right,
                                            diag_scale, out, ntiles);
}